// round 11
// baseline (speedup 1.0000x reference)
#include <cuda_runtime.h>
#include <cstdint>

// NoReFT on [B,768] fp32, regions start {0,752,184,568}, width 16.
// TMA G->S pipeline (3 stages x 12KB = 4 rows). Warp-owned half-rows:
// each warp patches the 32 edited floats inside its half-row (warp-local
// ordering only), then copies its 96 float4 with STG.128. One block sync
// per tile. 6 CTAs/SM.

#define T_ROWS 4
#define TILE_F (T_ROWS * 768)            // 3072 floats
#define TILE_F4 (TILE_F / 4)             // 768
#define TILE_BYTES (TILE_F * 4)          // 12288 B
#define STAGES 3
#define NT 256
#define MAXGRID 2048

#define SM_BAR (STAGES * TILE_F)         // even float idx -> 8B aligned
#define SM_BYTES (SM_BAR * 4 + STAGES * 8)

__device__ __forceinline__ void mbar_init(uint32_t a, uint32_t cnt) {
    asm volatile("mbarrier.init.shared.b64 [%0], %1;" :: "r"(a), "r"(cnt) : "memory");
}
__device__ __forceinline__ void mbar_expect_tx(uint32_t a, uint32_t bytes) {
    asm volatile("mbarrier.arrive.expect_tx.shared.b64 _, [%0], %1;" :: "r"(a), "r"(bytes) : "memory");
}
__device__ __forceinline__ void mbar_wait(uint32_t a, uint32_t parity) {
    asm volatile(
        "{\n\t.reg .pred P;\n\t"
        "LW_%=:\n\t"
        "mbarrier.try_wait.parity.acquire.cta.shared::cta.b64 P, [%0], %1, 0x989680;\n\t"
        "@P bra LD_%=;\n\t"
        "bra LW_%=;\n\t"
        "LD_%=:\n\t}"
        :: "r"(a), "r"(parity) : "memory");
}
__device__ __forceinline__ void bulk_ld(uint32_t dst, const void* src, uint32_t bytes, uint32_t bar) {
    asm volatile("cp.async.bulk.shared::cta.global.mbarrier::complete_tx::bytes [%0], [%1], %2, [%3];"
                 :: "r"(dst), "l"(src), "r"(bytes), "r"(bar) : "memory");
}
__device__ __forceinline__ int start_of(int g) {
    return g == 0 ? 0 : g == 1 ? 752 : g == 2 ? 184 : 568;
}

__global__ __launch_bounds__(NT, 6) void minireft_v11(
    const float* __restrict__ base, float* __restrict__ out,
    const float* __restrict__ Wp, const float* __restrict__ bp,
    const float* __restrict__ Ws, const float* __restrict__ bs,
    int B, int nTiles, int grid)
{
    extern __shared__ float smem[];
    const uint32_t smem_u32 = (uint32_t)__cvta_generic_to_shared(smem);
    const uint32_t bar0 = smem_u32 + SM_BAR * 4;

    const int tid  = threadIdx.x;
    const int w    = tid >> 5;           // warp 0..7 = half-row owner
    const int lane = tid & 31;

    // warp w -> tile row (w>>1), half (w&1). Regions per half:
    //   half 0: lanes 0-15 -> region 0 (start 0), lanes 16-31 -> region 2 (184)
    //   half 1: lanes 0-15 -> region 3 (568),     lanes 16-31 -> region 1 (752)
    const int prow = w >> 1;
    const int g = (w & 1) ? ((lane < 16) ? 3 : 1) : ((lane < 16) ? 0 : 2);
    const int l = lane & 15;
    const int xoff = prow * 768 + start_of(g);
    const int cb = 96 * w + lane;        // this thread's first copy chunk

    // ---- fold weights into scratch smem (stage-0 area, pre-pipeline) ----
    float* sM = smem;                    // [4][16][16]: sM[(g*16+e)*16+l]
    float* sC = smem + 1024;             // [4][16]
    for (int idx = tid; idx < 4 * 16 * 16; idx += NT) {
        int gg = idx >> 8, e = (idx >> 4) & 15, ll = idx & 15;
        float acc = 0.f;
        #pragma unroll
        for (int r = 0; r < 8; r++) {
            float wp = Wp[gg * 128 + r * 16 + e];
            float ws = Ws[gg * 128 + r * 16 + e];
            acc += (ws - wp) * Wp[gg * 128 + r * 16 + ll];
        }
        sM[idx] = acc;
    }
    for (int idx = tid; idx < 4 * 16; idx += NT) {
        int gg = idx >> 4, ll = idx & 15;
        float acc = 0.f;
        #pragma unroll
        for (int r = 0; r < 8; r++)
            acc += (bs[gg * 8 + r] - bp[gg * 8 + r]) * Wp[gg * 128 + r * 16 + ll];
        sC[idx] = acc;
    }
    __syncthreads();

    // registers: Mv[e] = sM[g][e][l] (+1 on diagonal), cl = sC[g][l]
    float Mv[16], cl;
    #pragma unroll
    for (int e = 0; e < 16; e++) Mv[e] = sM[(g * 16 + e) * 16 + l];
    Mv[l] += 1.0f;                       // folds "+x[l]" into the dot product
    cl = sC[g * 16 + l];
    __syncthreads();

    // ---- remainder rows (B % T_ROWS) on block 0 (scratch sM still valid) ----
    if (blockIdx.x == 0 && (B & (T_ROWS - 1))) {
        const long long remStart = (long long)nTiles * T_ROWS;
        for (long long row = remStart; row < B; row++) {
            for (int c = tid; c < 768; c += NT)
                out[row * 768 + c] = base[row * 768 + c];
            __syncthreads();
            if (tid < 64) {
                int gg = tid >> 4, ll = tid & 15;
                int st = start_of(gg);
                float d = sC[gg * 16 + ll];
                #pragma unroll
                for (int e = 0; e < 16; e++)
                    d += sM[(gg * 16 + e) * 16 + ll] * base[row * 768 + st + e];
                out[row * 768 + st + ll] = base[row * 768 + st + ll] + d;
            }
            __syncthreads();
        }
    }

    if (tid < STAGES) mbar_init(bar0 + tid * 8, 1);
    __syncthreads();

    const int bid = blockIdx.x;
    int count = 0;
    if (bid < nTiles) count = (nTiles - bid + grid - 1) / grid;

    // prologue: fill pipeline
    if (tid == 0) {
        int pre = count < STAGES ? count : STAGES;
        for (int k = 0; k < pre; k++) {
            long long tile = (long long)bid + (long long)k * grid;
            mbar_expect_tx(bar0 + k * 8, TILE_BYTES);
            bulk_ld(smem_u32 + (uint32_t)(k * TILE_BYTES),
                    base + tile * TILE_F, TILE_BYTES, bar0 + k * 8);
        }
    }

    int s = 0, p = 0;
    for (int k = 0; k < count; k++) {
        mbar_wait(bar0 + s * 8, p);

        float* sb = smem + s * TILE_F;

        // ---- warp-local patch of this lane's edited float ----
        {
            const float4* x4 = (const float4*)(sb + xoff);
            const float4 X0 = x4[0], X1 = x4[1], X2 = x4[2], X3 = x4[3];
            float d = cl;
            d += Mv[0]  * X0.x; d += Mv[1]  * X0.y;
            d += Mv[2]  * X0.z; d += Mv[3]  * X0.w;
            d += Mv[4]  * X1.x; d += Mv[5]  * X1.y;
            d += Mv[6]  * X1.z; d += Mv[7]  * X1.w;
            d += Mv[8]  * X2.x; d += Mv[9]  * X2.y;
            d += Mv[10] * X2.z; d += Mv[11] * X2.w;
            d += Mv[12] * X3.x; d += Mv[13] * X3.y;
            d += Mv[14] * X3.z; d += Mv[15] * X3.w;
            __syncwarp();                // all lanes read x before any write
            sb[xoff + l] = d;            // Mv diagonal carries the +x[l]
            __syncwarp();                // writes visible to the copy below
        }

        // ---- copy this warp's half-row (96 float4) ----
        {
            const float4* sb4 = (const float4*)sb;
            const long long tile = (long long)bid + (long long)k * grid;
            float4* op = (float4*)out + tile * TILE_F4;
            float4 v0 = sb4[cb];
            float4 v1 = sb4[cb + 32];
            float4 v2 = sb4[cb + 64];
            __stcs(op + cb, v0);
            __stcs(op + cb + 32, v1);
            __stcs(op + cb + 64, v2);
        }

        __syncthreads();                 // stage s fully consumed

        if (tid == 0 && k + STAGES < count) {
            long long nt = (long long)bid + (long long)(k + STAGES) * grid;
            mbar_expect_tx(bar0 + s * 8, TILE_BYTES);
            bulk_ld(smem_u32 + (uint32_t)(s * TILE_BYTES),
                    base + nt * TILE_F, TILE_BYTES, bar0 + s * 8);
        }

        if (++s == STAGES) { s = 0; p ^= 1; }
    }
}

extern "C" void kernel_launch(void* const* d_in, const int* in_sizes, int n_in,
                              void* d_out, int out_size)
{
    const float* base = (const float*)d_in[0];  // [1, B, 768]
    const float* Wp   = (const float*)d_in[1];
    const float* bp   = (const float*)d_in[2];
    const float* Ws   = (const float*)d_in[3];
    const float* bs   = (const float*)d_in[4];
    float* out = (float*)d_out;

    const int B = in_sizes[0] / 768;
    const int nTiles = B / T_ROWS;

    int grid = nTiles < MAXGRID ? (nTiles > 0 ? nTiles : 1) : MAXGRID;

    static int configured = 0;
    if (!configured) {
        cudaFuncSetAttribute(minireft_v11,
                             cudaFuncAttributeMaxDynamicSharedMemorySize, SM_BYTES);
        configured = 1;
    }

    minireft_v11<<<grid, NT, SM_BYTES>>>(base, out, Wp, bp, Ws, bs, B, nTiles, grid);
}